// round 1
// baseline (speedup 1.0000x reference)
#include <cuda_runtime.h>
#include <cuda_bf16.h>

#define N_NODES 50000
#define N_EDGES 800000
#define IN_DIM  128
#define HD      128   // N_HEAD * OUT_DIM
#define NHEAD   4
#define ODIM    32
#define IN_E    16

// ---------------- scratch (alloc-free rule: __device__ globals) ----------------
__device__ float g_featn[(size_t)N_NODES * HD];   // projected node features [N,128]
__device__ float g_el[N_NODES * NHEAD];
__device__ float g_er[N_NODES * NHEAD];
__device__ float g_e [(size_t)N_EDGES * NHEAD];   // logits, then exp values
__device__ int   g_menc[N_NODES * NHEAD];         // encoded segment max
__device__ float g_s [N_NODES * NHEAD];           // segment sums

// monotonic int encoding for float max via atomicMax (involution)
__device__ __forceinline__ int fenc(float f) {
    int b = __float_as_int(f);
    return b >= 0 ? b : (b ^ 0x7fffffff);
}
__device__ __forceinline__ float fdec(int b) {
    return __int_as_float(b >= 0 ? b : (b ^ 0x7fffffff));
}

// ---------------- K0: init out / max / sum ----------------
__global__ void k_init(float* __restrict__ out) {
    int i = blockIdx.x * blockDim.x + threadIdx.x;
    if (i < N_NODES * HD) out[i] = 0.0f;
    if (i < N_NODES * NHEAD) { g_menc[i] = (int)0x80000000; g_s[i] = 0.0f; }
}

// ---------------- K1: node projection GEMM + el/er ----------------
// block: 256 threads, 64 nodes per block, W staged in smem (padded stride 132)
#define NPB 64
#define GRP 8
#define WPAD 132

__global__ void k_gemm(const float* __restrict__ x, const float* __restrict__ W,
                       const float* __restrict__ al, const float* __restrict__ ar) {
    extern __shared__ float sm[];
    float* Wsm = sm;                     // 128 * 132
    float* xsm = sm + IN_DIM * WPAD;     // GRP * 128

    int tid = threadIdx.x;
    // load W [k][i] row-major into padded smem rows
    for (int e = tid; e < IN_DIM * HD; e += 256) {
        int k = e >> 7, i = e & 127;
        Wsm[k * WPAD + i] = W[e];
    }
    int k    = tid & 127;
    int quad = tid >> 7;                 // 0 or 1: which group of 4 nodes
    int lane = tid & 31;
    int h    = k >> 5;                   // warp covers exactly one head
    float alv = al[k], arv = ar[k];
    int base = blockIdx.x * NPB;
    __syncthreads();

    for (int g = 0; g < NPB; g += GRP) {
        __syncthreads();
        // stage 8 node rows
        for (int e = tid; e < GRP * IN_DIM; e += 256) {
            int n = base + g + (e >> 7);
            xsm[e] = (n < N_NODES) ? x[(size_t)n * IN_DIM + (e & 127)] : 0.0f;
        }
        __syncthreads();

        float acc0 = 0.f, acc1 = 0.f, acc2 = 0.f, acc3 = 0.f;
        const float4* wr = (const float4*)(Wsm + k * WPAD);
        const float4* x0 = (const float4*)(xsm + (quad * 4 + 0) * IN_DIM);
        const float4* x1 = (const float4*)(xsm + (quad * 4 + 1) * IN_DIM);
        const float4* x2 = (const float4*)(xsm + (quad * 4 + 2) * IN_DIM);
        const float4* x3 = (const float4*)(xsm + (quad * 4 + 3) * IN_DIM);
        #pragma unroll
        for (int i = 0; i < IN_DIM / 4; i++) {
            float4 w = wr[i];
            float4 a = x0[i]; float4 b = x1[i]; float4 c = x2[i]; float4 d = x3[i];
            acc0 += w.x*a.x + w.y*a.y + w.z*a.z + w.w*a.w;
            acc1 += w.x*b.x + w.y*b.y + w.z*b.z + w.w*b.w;
            acc2 += w.x*c.x + w.y*c.y + w.z*c.z + w.w*c.w;
            acc3 += w.x*d.x + w.y*d.y + w.z*d.z + w.w*d.w;
        }
        float accs[4] = {acc0, acc1, acc2, acc3};
        #pragma unroll
        for (int j = 0; j < 4; j++) {
            int n = base + g + quad * 4 + j;
            float v = accs[j];
            if (n < N_NODES) g_featn[(size_t)n * HD + k] = v;
            float sl = v * alv, sr = v * arv;
            #pragma unroll
            for (int o = 16; o; o >>= 1) {
                sl += __shfl_xor_sync(0xffffffffu, sl, o);
                sr += __shfl_xor_sync(0xffffffffu, sr, o);
            }
            if (lane == 0 && n < N_NODES) {
                g_el[n * NHEAD + h] = sl;
                g_er[n * NHEAD + h] = sr;
            }
        }
    }
}

// ---------------- K2: edge logits + leaky relu + segment max ----------------
__global__ void k_logit(const float* __restrict__ fe, const int* __restrict__ src,
                        const int* __restrict__ dst, const float* __restrict__ ae) {
    __shared__ float aesm[NHEAD * IN_E];
    if (threadIdx.x < NHEAD * IN_E) aesm[threadIdx.x] = ae[threadIdx.x];
    __syncthreads();
    int e = blockIdx.x * blockDim.x + threadIdx.x;
    if (e >= N_EDGES) return;
    int s = src[e], dnode = dst[e];

    const float4* fr = (const float4*)(fe + (size_t)e * IN_E);
    float4 f0 = fr[0], f1 = fr[1], f2 = fr[2], f3 = fr[3];

    float lg[4];
    #pragma unroll
    for (int h = 0; h < NHEAD; h++) {
        const float* a = aesm + h * IN_E;
        float ee = f0.x*a[0]  + f0.y*a[1]  + f0.z*a[2]  + f0.w*a[3]
                 + f1.x*a[4]  + f1.y*a[5]  + f1.z*a[6]  + f1.w*a[7]
                 + f2.x*a[8]  + f2.y*a[9]  + f2.z*a[10] + f2.w*a[11]
                 + f3.x*a[12] + f3.y*a[13] + f3.z*a[14] + f3.w*a[15];
        float v = g_el[s * NHEAD + h] + g_er[dnode * NHEAD + h] + ee;
        lg[h] = v > 0.0f ? v : 0.2f * v;                 // leaky relu 0.2
        atomicMax(&g_menc[dnode * NHEAD + h], fenc(lg[h]));
    }
    float4 st = make_float4(lg[0], lg[1], lg[2], lg[3]);
    ((float4*)g_e)[e] = st;
}

// ---------------- K3: exp(e - m[dst]) + segment sum ----------------
__global__ void k_expsum(const int* __restrict__ dst) {
    int e = blockIdx.x * blockDim.x + threadIdx.x;
    if (e >= N_EDGES) return;
    int dnode = dst[e];
    float4 lv = ((const float4*)g_e)[e];
    float l[4] = {lv.x, lv.y, lv.z, lv.w};
    float ex[4];
    #pragma unroll
    for (int h = 0; h < NHEAD; h++) {
        float m = fdec(g_menc[dnode * NHEAD + h]);
        ex[h] = __expf(l[h] - m);
        atomicAdd(&g_s[dnode * NHEAD + h], ex[h]);
    }
    ((float4*)g_e)[e] = make_float4(ex[0], ex[1], ex[2], ex[3]);
}

// ---------------- K4: normalize + weighted scatter-aggregate ----------------
// one warp per edge; lane l handles 4 contiguous output cols
__global__ void k_agg(const int* __restrict__ src, const int* __restrict__ dst,
                      float* __restrict__ out) {
    int gw = (blockIdx.x * blockDim.x + threadIdx.x) >> 5;
    if (gw >= N_EDGES) return;
    int lane = threadIdx.x & 31;
    int e = gw;
    int s = src[e], dnode = dst[e];
    int h = lane >> 3;                                   // cols [lane*4, +4) -> head
    float a = g_e[(size_t)e * NHEAD + h] / g_s[dnode * NHEAD + h];
    int c = lane * 4;
    float4 f = *(const float4*)(g_featn + (size_t)s * HD + c);
    float* o = out + (size_t)dnode * HD + c;
    atomicAdd(o + 0, f.x * a);
    atomicAdd(o + 1, f.y * a);
    atomicAdd(o + 2, f.z * a);
    atomicAdd(o + 3, f.w * a);
}

// ---------------- launch ----------------
extern "C" void kernel_launch(void* const* d_in, const int* in_sizes, int n_in,
                              void* d_out, int out_size) {
    const float* feats_node = (const float*)d_in[0];
    const float* feats_edge = (const float*)d_in[1];
    const int*   src        = (const int*)d_in[2];
    const int*   dst        = (const int*)d_in[3];
    const float* W_node     = (const float*)d_in[4];
    const float* attn_l     = (const float*)d_in[5];
    const float* attn_r     = (const float*)d_in[6];
    const float* attn_e     = (const float*)d_in[7];
    float* out = (float*)d_out;

    int smem = (IN_DIM * WPAD + GRP * IN_DIM) * sizeof(float);   // ~71.7 KB
    cudaFuncSetAttribute(k_gemm, cudaFuncAttributeMaxDynamicSharedMemorySize, smem);

    // K0: init
    {
        int n = N_NODES * HD;
        k_init<<<(n + 255) / 256, 256>>>(out);
    }
    // K1: projection + el/er
    {
        int grid = (N_NODES + NPB - 1) / NPB;
        k_gemm<<<grid, 256, smem>>>(feats_node, W_node, attn_l, attn_r);
    }
    // K2: logits + segment max
    k_logit<<<(N_EDGES + 255) / 256, 256>>>(feats_edge, src, dst, attn_e);
    // K3: exp + segment sum
    k_expsum<<<(N_EDGES + 255) / 256, 256>>>(dst);
    // K4: aggregate
    {
        long long warps = N_EDGES;
        int grid = (int)((warps * 32 + 255) / 256);
        k_agg<<<grid, 256>>>(src, dst, out);
    }
}

// round 2
// speedup vs baseline: 2.4183x; 2.4183x over previous
#include <cuda_runtime.h>
#include <cuda_bf16.h>

#define N_NODES 50000
#define N_EDGES 800000
#define IN_DIM  128
#define HD      128   // N_HEAD * OUT_DIM
#define NHEAD   4
#define IN_E    16

#define SCAN_BS 512
#define NBLK    ((N_NODES + SCAN_BS - 1) / SCAN_BS)   // 98

// ---------------- scratch (__device__ globals; alloc-free rule) ----------------
__device__ float g_featn[(size_t)N_NODES * HD];   // projected node features [N,128]
__device__ float g_el[N_NODES * NHEAD];
__device__ float g_er[N_NODES * NHEAD];
__device__ float g_lg[(size_t)N_EDGES * NHEAD];   // per-edge leaky-relu logits
__device__ int   g_cnt[N_NODES];                  // in-degree histogram
__device__ int   g_off[N_NODES + 1];              // CSR offsets (exclusive scan)
__device__ int   g_cur[N_NODES];                  // scatter cursors
__device__ int2  g_csr[N_EDGES];                  // {edge_id, src_node} sorted by dst
__device__ int   g_bsum[NBLK];
__device__ int   g_bpre[NBLK];

// ---------------- f32x2 packed-FMA helpers (sm_100+) ----------------
typedef unsigned long long ull;
__device__ __forceinline__ void ffma2(ull& d, ull a, ull b) {
    asm("fma.rn.f32x2 %0, %1, %2, %0;" : "+l"(d) : "l"(a), "l"(b));
}
__device__ __forceinline__ ull pack2(float v) {
    ull r; asm("mov.b64 %0, {%1, %1};" : "=l"(r) : "f"(v)); return r;
}

// ---------------- K0: zero histogram ----------------
__global__ void k_init() {
    int i = blockIdx.x * blockDim.x + threadIdx.x;
    if (i < N_NODES) g_cnt[i] = 0;
}

// ---------------- K1: node projection SGEMM (f32x2 packed) ----------------
// 256 threads; block tile 128 nodes x 128 outs; thread tile 8x8.
// Wsm[k][out] and Xs[k][node], both stride 132 floats. smem = 2*128*132*4 = 135168 B.
#define GSTR 132
__global__ void k_gemm(const float* __restrict__ x, const float* __restrict__ W) {
    extern __shared__ float sm[];
    float* Wsm = sm;                    // [k*132 + out]
    float* Xs  = sm + IN_DIM * GSTR;    // [k*132 + n_local]
    int tid = threadIdx.x;
    int base = blockIdx.x * 128;

    // W[out][k] -> Wsm[k][out]  (coalesced gmem reads)
    for (int i = tid; i < 128 * 128; i += 256) {
        int out = i >> 7, k = i & 127;
        Wsm[k * GSTR + out] = W[i];
    }
    // x[node][k] -> Xs[k][n_local]
    for (int i = tid; i < 128 * 128; i += 256) {
        int n = i >> 7, k = i & 127;
        int gn = base + n;
        Xs[k * GSTR + n] = (gn < N_NODES) ? x[(size_t)gn * IN_DIM + k] : 0.0f;
    }
    __syncthreads();

    int ty = tid >> 4, tx = tid & 15;         // ty: 8 nodes, tx: 8 outs
    int n0 = ty * 8, c0 = tx * 8;
    ull acc[8][4];
    #pragma unroll
    for (int j = 0; j < 8; j++)
        #pragma unroll
        for (int p = 0; p < 4; p++) acc[j][p] = 0ull;

    #pragma unroll 4
    for (int k = 0; k < IN_DIM; k++) {
        const float* xr = Xs  + k * GSTR + n0;
        const float* wr = Wsm + k * GSTR + c0;
        ulonglong2 w0 = *(const ulonglong2*)(wr);      // cols c0..c0+3
        ulonglong2 w1 = *(const ulonglong2*)(wr + 4);  // cols c0+4..c0+7
        float4 xa = *(const float4*)(xr);
        float4 xb = *(const float4*)(xr + 4);
        float xv[8] = {xa.x, xa.y, xa.z, xa.w, xb.x, xb.y, xb.z, xb.w};
        #pragma unroll
        for (int j = 0; j < 8; j++) {
            ull px = pack2(xv[j]);
            ffma2(acc[j][0], px, w0.x);
            ffma2(acc[j][1], px, w0.y);
            ffma2(acc[j][2], px, w1.x);
            ffma2(acc[j][3], px, w1.y);
        }
    }
    #pragma unroll
    for (int j = 0; j < 8; j++) {
        int node = base + n0 + j;
        if (node < N_NODES) {
            ull* o = (ull*)(g_featn + (size_t)node * HD + c0);
            o[0] = acc[j][0]; o[1] = acc[j][1]; o[2] = acc[j][2]; o[3] = acc[j][3];
        }
    }
}

// ---------------- K2: per-node attention logits el/er ----------------
// warp per node; lane covers 4 cols (one head per 8-lane group)
__global__ void k_attn(const float* __restrict__ al, const float* __restrict__ ar) {
    int w = (blockIdx.x * blockDim.x + threadIdx.x) >> 5;
    if (w >= N_NODES) return;
    int lane = threadIdx.x & 31;
    int c = lane * 4, h = lane >> 3;
    float4 f = *(const float4*)(g_featn + (size_t)w * HD + c);
    float4 a = *(const float4*)(al + c);
    float4 b = *(const float4*)(ar + c);
    float pl = f.x * a.x + f.y * a.y + f.z * a.z + f.w * a.w;
    float pr = f.x * b.x + f.y * b.y + f.z * b.z + f.w * b.w;
    #pragma unroll
    for (int o = 1; o < 8; o <<= 1) {
        pl += __shfl_xor_sync(0xffffffffu, pl, o);
        pr += __shfl_xor_sync(0xffffffffu, pr, o);
    }
    if ((lane & 7) == 0) {
        g_el[w * NHEAD + h] = pl;
        g_er[w * NHEAD + h] = pr;
    }
}

// ---------------- K3: edge logits + leaky relu + degree histogram ----------------
__global__ void k_logit(const float* __restrict__ fe, const int* __restrict__ src,
                        const int* __restrict__ dst, const float* __restrict__ ae) {
    __shared__ float aesm[NHEAD * IN_E];
    if (threadIdx.x < NHEAD * IN_E) aesm[threadIdx.x] = ae[threadIdx.x];
    __syncthreads();
    int e = blockIdx.x * blockDim.x + threadIdx.x;
    if (e >= N_EDGES) return;
    int s = src[e], d = dst[e];

    const float4* fr = (const float4*)(fe + (size_t)e * IN_E);
    float4 f0 = fr[0], f1 = fr[1], f2 = fr[2], f3 = fr[3];
    float4 elv = *(const float4*)(g_el + s * NHEAD);
    float4 erv = *(const float4*)(g_er + d * NHEAD);
    float els[4] = {elv.x, elv.y, elv.z, elv.w};
    float ers[4] = {erv.x, erv.y, erv.z, erv.w};

    float lg[4];
    #pragma unroll
    for (int h = 0; h < NHEAD; h++) {
        const float* a = aesm + h * IN_E;
        float ee = f0.x*a[0]  + f0.y*a[1]  + f0.z*a[2]  + f0.w*a[3]
                 + f1.x*a[4]  + f1.y*a[5]  + f1.z*a[6]  + f1.w*a[7]
                 + f2.x*a[8]  + f2.y*a[9]  + f2.z*a[10] + f2.w*a[11]
                 + f3.x*a[12] + f3.y*a[13] + f3.z*a[14] + f3.w*a[15];
        float v = els[h] + ers[h] + ee;
        lg[h] = v > 0.0f ? v : 0.2f * v;                // leaky relu 0.2
    }
    ((float4*)g_lg)[e] = make_float4(lg[0], lg[1], lg[2], lg[3]);
    atomicAdd(&g_cnt[d], 1);
}

// ---------------- K4a/b/c: exclusive scan of degrees -> CSR offsets ----------------
__global__ void k_scan1() {
    __shared__ int s[SCAN_BS];
    int t = threadIdx.x;
    int i = blockIdx.x * SCAN_BS + t;
    int v = (i < N_NODES) ? g_cnt[i] : 0;
    s[t] = v; __syncthreads();
    for (int o = 1; o < SCAN_BS; o <<= 1) {
        int u = (t >= o) ? s[t - o] : 0;
        __syncthreads();
        s[t] += u;
        __syncthreads();
    }
    if (i < N_NODES) g_off[i] = s[t] - v;              // exclusive
    if (t == SCAN_BS - 1) g_bsum[blockIdx.x] = s[t];
}
__global__ void k_scan2() {
    __shared__ int s[128];
    int t = threadIdx.x;
    int v = (t < NBLK) ? g_bsum[t] : 0;
    s[t] = v; __syncthreads();
    for (int o = 1; o < 128; o <<= 1) {
        int u = (t >= o) ? s[t - o] : 0;
        __syncthreads();
        s[t] += u;
        __syncthreads();
    }
    if (t < NBLK) g_bpre[t] = s[t] - v;                // exclusive
}
__global__ void k_scan3() {
    int i = blockIdx.x * SCAN_BS + threadIdx.x;
    if (i == 0) g_off[N_NODES] = N_EDGES;
    if (i < N_NODES) {
        int v = g_off[i] + g_bpre[blockIdx.x];
        g_off[i] = v;
        g_cur[i] = v;
    }
}

// ---------------- K5: scatter edges into CSR (sorted by dst) ----------------
__global__ void k_scatter(const int* __restrict__ src, const int* __restrict__ dst) {
    int e = blockIdx.x * blockDim.x + threadIdx.x;
    if (e >= N_EDGES) return;
    int d = dst[e];
    int pos = atomicAdd(&g_cur[d], 1);
    g_csr[pos] = make_int2(e, src[e]);
}

// ---------------- K6: per-dst-node softmax + weighted aggregate ----------------
// warp per node; lane handles 4 output cols; no output atomics.
__global__ void k_node(float* __restrict__ out) {
    int w = (blockIdx.x * blockDim.x + threadIdx.x) >> 5;
    if (w >= N_NODES) return;
    int lane = threadIdx.x & 31;
    int c = lane * 4, h = lane >> 3;
    float* orow = out + (size_t)w * HD + c;

    int beg = g_off[w], end = g_off[w + 1];
    if (beg == end) {                                   // zero-degree node
        *(float4*)orow = make_float4(0.f, 0.f, 0.f, 0.f);
        return;
    }
    const float NEG = -3.4e38f;
    // pass 1: per-head max over in-edges
    float4 mx = make_float4(NEG, NEG, NEG, NEG);
    for (int p = beg + lane; p < end; p += 32) {
        float4 lg = ((const float4*)g_lg)[g_csr[p].x];
        mx.x = fmaxf(mx.x, lg.x); mx.y = fmaxf(mx.y, lg.y);
        mx.z = fmaxf(mx.z, lg.z); mx.w = fmaxf(mx.w, lg.w);
    }
    #pragma unroll
    for (int o = 16; o; o >>= 1) {
        mx.x = fmaxf(mx.x, __shfl_xor_sync(0xffffffffu, mx.x, o));
        mx.y = fmaxf(mx.y, __shfl_xor_sync(0xffffffffu, mx.y, o));
        mx.z = fmaxf(mx.z, __shfl_xor_sync(0xffffffffu, mx.z, o));
        mx.w = fmaxf(mx.w, __shfl_xor_sync(0xffffffffu, mx.w, o));
    }
    // pass 2: per-head sum of exp
    float4 sm = make_float4(0.f, 0.f, 0.f, 0.f);
    for (int p = beg + lane; p < end; p += 32) {
        float4 lg = ((const float4*)g_lg)[g_csr[p].x];
        sm.x += __expf(lg.x - mx.x); sm.y += __expf(lg.y - mx.y);
        sm.z += __expf(lg.z - mx.z); sm.w += __expf(lg.w - mx.w);
    }
    #pragma unroll
    for (int o = 16; o; o >>= 1) {
        sm.x += __shfl_xor_sync(0xffffffffu, sm.x, o);
        sm.y += __shfl_xor_sync(0xffffffffu, sm.y, o);
        sm.z += __shfl_xor_sync(0xffffffffu, sm.z, o);
        sm.w += __shfl_xor_sync(0xffffffffu, sm.w, o);
    }
    float mh = (h < 2) ? (h == 0 ? mx.x : mx.y) : (h == 2 ? mx.z : mx.w);
    float sh = (h < 2) ? (h == 0 ? sm.x : sm.y) : (h == 2 ? sm.z : sm.w);
    float inv = 1.0f / sh;
    // pass 3: weighted gather-accumulate
    float4 acc = make_float4(0.f, 0.f, 0.f, 0.f);
    for (int p = beg; p < end; p++) {
        int2 es = g_csr[p];                              // uniform across warp
        float a = __expf(g_lg[(size_t)es.x * NHEAD + h] - mh) * inv;
        float4 f = *(const float4*)(g_featn + (size_t)es.y * HD + c);
        acc.x += f.x * a; acc.y += f.y * a; acc.z += f.z * a; acc.w += f.w * a;
    }
    *(float4*)orow = acc;
}

// ---------------- launch ----------------
extern "C" void kernel_launch(void* const* d_in, const int* in_sizes, int n_in,
                              void* d_out, int out_size) {
    const float* feats_node = (const float*)d_in[0];
    const float* feats_edge = (const float*)d_in[1];
    const int*   src        = (const int*)d_in[2];
    const int*   dst        = (const int*)d_in[3];
    const float* W_node     = (const float*)d_in[4];
    const float* attn_l     = (const float*)d_in[5];
    const float* attn_r     = (const float*)d_in[6];
    const float* attn_e     = (const float*)d_in[7];
    float* out = (float*)d_out;

    int gsm = 2 * IN_DIM * GSTR * sizeof(float);        // 135168 B
    static int configured = 0;
    if (!configured) {
        cudaFuncSetAttribute(k_gemm, cudaFuncAttributeMaxDynamicSharedMemorySize, gsm);
        configured = 1;
    }

    k_init<<<(N_NODES + 255) / 256, 256>>>();
    k_gemm<<<(N_NODES + 127) / 128, 256, gsm>>>(feats_node, W_node);
    k_attn<<<(N_NODES * 32 + 255) / 256, 256>>>(attn_l, attn_r);
    k_logit<<<(N_EDGES + 255) / 256, 256>>>(feats_edge, src, dst, attn_e);
    k_scan1<<<NBLK, SCAN_BS>>>();
    k_scan2<<<1, 128>>>();
    k_scan3<<<NBLK, SCAN_BS>>>();
    k_scatter<<<(N_EDGES + 255) / 256, 256>>>(src, dst);
    k_node<<<(N_NODES * 32 + 255) / 256, 256>>>(out);
}